// round 11
// baseline (speedup 1.0000x reference)
#include <cuda_runtime.h>
#include <cuda_bf16.h>
#include <math.h>

#define BATCH 2
#define NPTS  8192
#define CH    128
#define KNN   8
#define MTOT  (BATCH * NPTS)
#define G     32
#define NC    (G * G * G)        // 32768 cells per batch
#define NCT   (BATCH * NC)       // 65536 total

// ---------------- scratch (no allocations allowed) ----------------
__device__ float    g_q[MTOT * CH];
__device__ float    g_k[MTOT * CH];
__device__ float    g_v[MTOT * CH];
__device__ float    g_agg[MTOT * CH];
__device__ int      g_idx[MTOT * KNN];
__device__ unsigned g_bbmin[6];          // encoded per-batch min x,y,z
__device__ unsigned g_bbmax[6];          // encoded per-batch max x,y,z
__device__ float    g_grid[16];          // per batch: minx,miny,minz, invx,invy,invz, emin, pad
__device__ int      g_cnt[NCT];
__device__ int      g_cellstart[NCT + 1];
__device__ int      g_cursor[NCT];
__device__ float4   g_pts[MTOT];         // sorted by cell: x,y,z, bits(local idx)

// ---------------- order-preserving float<->uint for atomic min/max ----------------
__device__ __forceinline__ unsigned encf(float f) {
    unsigned u = __float_as_uint(f);
    return (u & 0x80000000u) ? ~u : (u | 0x80000000u);
}
__device__ __forceinline__ float decf(unsigned u) {
    unsigned v = (u & 0x80000000u) ? (u ^ 0x80000000u) : ~u;
    return __uint_as_float(v);
}

// cell index; MUST be used identically by count/scatter/search
__device__ __forceinline__ int cell_of(int b, float x, float y, float z,
                                       int& cx, int& cy, int& cz)
{
    const float* gp = g_grid + b * 8;
    cx = (int)((x - gp[0]) * gp[3]); if (cx > G - 1) cx = G - 1; if (cx < 0) cx = 0;
    cy = (int)((y - gp[1]) * gp[4]); if (cy > G - 1) cy = G - 1; if (cy < 0) cy = 0;
    cz = (int)((z - gp[2]) * gp[5]); if (cz > G - 1) cz = G - 1; if (cz < 0) cz = 0;
    return b * NC + (cz * G + cy) * G + cx;
}

// ---------------- grid build kernels ----------------
__global__ __launch_bounds__(256) void bbox_kernel(const float* __restrict__ coords)
{
    __shared__ unsigned smn[3][256], smx[3][256];
    int tid = threadIdx.x;
    int i = blockIdx.x * 256 + tid;
    float x = coords[i * 3 + 0], y = coords[i * 3 + 1], z = coords[i * 3 + 2];
    smn[0][tid] = encf(x); smn[1][tid] = encf(y); smn[2][tid] = encf(z);
    smx[0][tid] = encf(x); smx[1][tid] = encf(y); smx[2][tid] = encf(z);
    __syncthreads();
    for (int s = 128; s; s >>= 1) {
        if (tid < s) {
#pragma unroll
            for (int a = 0; a < 3; a++) {
                smn[a][tid] = min(smn[a][tid], smn[a][tid + s]);
                smx[a][tid] = max(smx[a][tid], smx[a][tid + s]);
            }
        }
        __syncthreads();
    }
    if (tid == 0) {
        int b = blockIdx.x >> 5;            // 32 CTAs per batch
#pragma unroll
        for (int a = 0; a < 3; a++) {
            atomicMin(&g_bbmin[b * 3 + a], smn[a][0]);
            atomicMax(&g_bbmax[b * 3 + a], smx[a][0]);
        }
    }
}

__global__ void grid_params_kernel()
{
    int b = threadIdx.x;
    if (b >= BATCH) return;
    float emin = 1e30f;
#pragma unroll
    for (int a = 0; a < 3; a++) {
        float mn  = decf(g_bbmin[b * 3 + a]);
        float mx  = decf(g_bbmax[b * 3 + a]);
        float ext = (mx - mn) * 1.000002f + 1e-12f;
        g_grid[b * 8 + a]     = mn;
        g_grid[b * 8 + 3 + a] = (float)G / ext;
        float e = ext / (float)G;
        if (e < emin) emin = e;
    }
    g_grid[b * 8 + 6] = emin;
}

__global__ __launch_bounds__(256) void count_kernel(const float* __restrict__ coords)
{
    int i = blockIdx.x * 256 + threadIdx.x;
    int b = i >> 13;
    int cx, cy, cz;
    int cell = cell_of(b, coords[i * 3], coords[i * 3 + 1], coords[i * 3 + 2], cx, cy, cz);
    atomicAdd(&g_cnt[cell], 1);
}

__global__ __launch_bounds__(1024) void scan_kernel()
{
    __shared__ int ss[1024];
    int tid = threadIdx.x;
    int base = tid * (NCT / 1024);          // 64 cells each
    int sum = 0;
#pragma unroll 4
    for (int j = 0; j < NCT / 1024; j++) sum += g_cnt[base + j];
    ss[tid] = sum;
    __syncthreads();
    for (int off = 1; off < 1024; off <<= 1) {
        int v = (tid >= off) ? ss[tid - off] : 0;
        __syncthreads();
        ss[tid] += v;
        __syncthreads();
    }
    int run = ss[tid] - sum;                // exclusive
#pragma unroll 4
    for (int j = 0; j < NCT / 1024; j++) {
        g_cellstart[base + j] = run;
        g_cursor[base + j]    = run;
        run += g_cnt[base + j];
    }
    if (tid == 1023) g_cellstart[NCT] = MTOT;
}

__global__ __launch_bounds__(256) void scatter_kernel(const float* __restrict__ coords)
{
    int i = blockIdx.x * 256 + threadIdx.x;
    int b = i >> 13;
    float x = coords[i * 3], y = coords[i * 3 + 1], z = coords[i * 3 + 2];
    int cx, cy, cz;
    int cell = cell_of(b, x, y, z, cx, cy, cz);
    int pos = atomicAdd(&g_cursor[cell], 1);
    g_pts[pos] = make_float4(x, y, z, __int_as_float(i & (NPTS - 1)));
}

// ---------------- grid KNN: one warp per query, expanding Chebyshev shells ------
// Exact: after scanning shell rho, any unscanned point is >= rho*emin away.
__global__ __launch_bounds__(256) void knn_grid_kernel(const float* __restrict__ coords,
                                                       int* __restrict__ out_idx)
{
    __shared__ int spre[8][32], sadj[8][32];
    const unsigned full = 0xffffffffu;
    const int wslot = threadIdx.x >> 5;
    const int lane  = threadIdx.x & 31;
    const int gq    = blockIdx.x * 8 + wslot;
    const int b     = gq >> 13;
    const int q     = gq & (NPTS - 1);
    int* pre_s = spre[wslot];
    int* adj_s = sadj[wslot];

    const float qx = coords[(size_t)(b * NPTS + q) * 3 + 0];
    const float qy = coords[(size_t)(b * NPTS + q) * 3 + 1];
    const float qz = coords[(size_t)(b * NPTS + q) * 3 + 2];
    int cx, cy, cz;
    cell_of(b, qx, qy, qz, cx, cy, cz);
    const float emin = g_grid[b * 8 + 6];

    float val = 3.0e38f, thr = 3.0e38f;
    int idx = -1;

    for (int rho = 0; ; rho++) {
        int side = 2 * rho + 1;
        int s2   = side * side;
        int cube = s2 * side;
        for (int base0 = 0; base0 < cube; base0 += 32) {
            int t = base0 + lane;
            int cnt = 0, cstart = 0;
            if (t < cube) {
                int dz = t / s2, rem = t - dz * s2;
                int dy = rem / side, dx = rem - dy * side;
                dx -= rho; dy -= rho; dz -= rho;
                int ch = max(abs(dx), max(abs(dy), abs(dz)));
                int ccx = cx + dx, ccy = cy + dy, ccz = cz + dz;
                if (ch == rho && ccx >= 0 && ccx < G && ccy >= 0 && ccy < G
                    && ccz >= 0 && ccz < G) {
                    int cid = b * NC + (ccz * G + ccy) * G + ccx;
                    cstart = g_cellstart[cid];
                    cnt    = g_cellstart[cid + 1] - cstart;
                }
            }
            // warp exclusive prefix of cnt
            int pre = cnt;
#pragma unroll
            for (int o = 1; o < 32; o <<= 1) {
                int n = __shfl_up_sync(full, pre, o);
                if (lane >= o) pre += n;
            }
            int total = __shfl_sync(full, pre, 31);
            pre -= cnt;
            __syncwarp();
            pre_s[lane] = pre;
            adj_s[lane] = cstart - pre;
            __syncwarp();

            int nr = (total + 31) >> 5;
            for (int r = 0; r < nr; r++) {
                int t2 = r * 32 + lane;
                float d2 = 3.0e38f;
                int pidx = 0;
                if (t2 < total) {
                    int lo = 0, hi = 31;
#pragma unroll
                    for (int s = 0; s < 5; s++) {        // largest j: pre_s[j] <= t2
                        int mid = (lo + hi + 1) >> 1;
                        if (pre_s[mid] <= t2) lo = mid; else hi = mid - 1;
                    }
                    float4 c = g_pts[adj_s[lo] + t2];
                    float dxx = qx - c.x, dyy = qy - c.y, dzz = qz - c.z;
                    d2 = fmaf(dzz, dzz, fmaf(dyy, dyy, dxx * dxx));
                    pidx = __float_as_int(c.w);
                }
                unsigned m = __ballot_sync(full, d2 < thr);
                while (m) {
                    int src = __ffs(m) - 1;
                    m &= m - 1;
                    float dn = __shfl_sync(full, d2, src);
                    if (dn < thr) {                      // warp-uniform
                        int in = __shfl_sync(full, pidx, src);
                        float pv = __shfl_up_sync(full, val, 1);
                        int   pi = __shfl_up_sync(full, idx, 1);
                        unsigned le = __ballot_sync(full, val <= dn);
                        int pos = __popc(le & 0xff);
                        if (lane == pos)                 { val = dn; idx = in; }
                        else if (lane > pos && lane < 8) { val = pv; idx = pi; }
                        thr = __shfl_sync(full, val, 7);
                    }
                }
            }
        }
        float bound = (float)rho * emin;
        if (thr <= bound * bound * 0.9996f) break;       // exact termination
        if (rho >= G - 1) break;                         // scanned everything
    }

    if (lane < KNN)
        out_idx[((size_t)b * NPTS + q) * KNN + lane] = idx;
}

// ---------------- fp32 -> (hi,lo) bf16 split helpers ----------------
__device__ __forceinline__ void split_bf16(float x, unsigned short& h, unsigned short& l) {
    __nv_bfloat16 hb = __float2bfloat16(x);
    float hf = __bfloat162float(hb);
    __nv_bfloat16 lb = __float2bfloat16(x - hf);
    h = __bfloat16_as_ushort(hb);
    l = __bfloat16_as_ushort(lb);
}
__device__ __forceinline__ unsigned pack_hilo(float x) {
    unsigned short h, l; split_bf16(x, h, l);
    return ((unsigned)l << 16) | (unsigned)h;
}
__device__ __forceinline__ void pack_w(float x, unsigned& p0, unsigned& p1) {
    unsigned short h, l; split_bf16(x, h, l);
    p0 = ((unsigned)h << 16) | h;
    p1 = ((unsigned)l << 16) | l;
}

// ---------------- tensor-core GEMM:  Y = X @ W^T via bf16 split-K ----------------
__device__ __forceinline__ void mma_gemm_tile(const float* __restrict__ X,
                                              const float* __restrict__ Wf,
                                              float* __restrict__ Y, int m0)
{
    __shared__ __align__(16) unsigned char xs[64 * 144];
    __shared__ __align__(16) unsigned char ws[128 * 144];
    const int tid  = threadIdx.x;
    const int lane = tid & 31;
    const int warp = tid >> 5;
    const int wm   = warp >> 2;
    const int wn   = warp & 3;
    const int g    = lane >> 2;
    const int c4   = lane & 3;

    float acc[2][4][4];
#pragma unroll
    for (int i = 0; i < 2; i++)
#pragma unroll
        for (int t = 0; t < 4; t++)
#pragma unroll
            for (int r = 0; r < 4; r++) acc[i][t][r] = 0.f;

    for (int kc = 0; kc < 8; kc++) {
        __syncthreads();
#pragma unroll
        for (int i = 0; i < 2; i++) {
            int s  = tid + i * 256;
            int r  = s >> 3;
            int f4 = s & 7;
            float2 xv = *(const float2*)(X + (size_t)(m0 + r) * CH + kc * 16 + f4 * 2);
            unsigned p0 = pack_hilo(xv.x), p1 = pack_hilo(xv.y);
            *(uint4*)(xs + r * 144 + f4 * 16) = make_uint4(p0, p0, p1, p1);
        }
#pragma unroll
        for (int i = 0; i < 4; i++) {
            int s  = tid + i * 256;
            int r  = s >> 3;
            int f4 = s & 7;
            float2 wv = *(const float2*)(Wf + (size_t)r * CH + kc * 16 + f4 * 2);
            unsigned a0, a1, b0, b1;
            pack_w(wv.x, a0, a1);
            pack_w(wv.y, b0, b1);
            *(uint4*)(ws + r * 144 + f4 * 16) = make_uint4(a0, a1, b0, b1);
        }
        __syncthreads();
#pragma unroll
        for (int ks = 0; ks < 4; ks++) {
            unsigned a[2][4], b[4][2];
#pragma unroll
            for (int i = 0; i < 2; i++)
#pragma unroll
                for (int j = 0; j < 4; j++) {
                    int row = wm * 32 + i * 16 + g + 8 * (j & 1);
                    int off = ks * 32 + (j >> 1) * 16 + c4 * 4;
                    a[i][j] = *(const unsigned*)(xs + row * 144 + off);
                }
#pragma unroll
            for (int t = 0; t < 4; t++)
#pragma unroll
                for (int r = 0; r < 2; r++) {
                    int n   = wn * 32 + t * 8 + g;
                    int off = ks * 32 + r * 16 + c4 * 4;
                    b[t][r] = *(const unsigned*)(ws + n * 144 + off);
                }
#pragma unroll
            for (int i = 0; i < 2; i++)
#pragma unroll
                for (int t = 0; t < 4; t++)
                    asm volatile(
                        "mma.sync.aligned.m16n8k16.row.col.f32.bf16.bf16.f32 "
                        "{%0,%1,%2,%3}, {%4,%5,%6,%7}, {%8,%9}, {%0,%1,%2,%3};"
                        : "+f"(acc[i][t][0]), "+f"(acc[i][t][1]),
                          "+f"(acc[i][t][2]), "+f"(acc[i][t][3])
                        : "r"(a[i][0]), "r"(a[i][1]), "r"(a[i][2]), "r"(a[i][3]),
                          "r"(b[t][0]), "r"(b[t][1]));
        }
    }
#pragma unroll
    for (int i = 0; i < 2; i++)
#pragma unroll
        for (int t = 0; t < 4; t++) {
            int row = m0 + wm * 32 + i * 16 + g;
            int col = wn * 32 + t * 8 + 2 * c4;
            *(float2*)(Y + (size_t)row * CH + col)       = make_float2(acc[i][t][0], acc[i][t][1]);
            *(float2*)(Y + (size_t)(row + 8) * CH + col) = make_float2(acc[i][t][2], acc[i][t][3]);
        }
}

__global__ __launch_bounds__(256) void qkv_mma_kernel(const float* __restrict__ feats,
                                                      const float* __restrict__ Wq,
                                                      const float* __restrict__ Wk,
                                                      const float* __restrict__ Wv)
{
    int w = blockIdx.y;
    const float* W = (w == 0) ? Wq : (w == 1) ? Wk : Wv;
    float* Y = (w == 0) ? g_q : (w == 1) ? g_k : g_v;
    mma_gemm_tile(feats, W, Y, blockIdx.x * 64);
}

__global__ __launch_bounds__(256) void out_mma_kernel(const float* __restrict__ Wo,
                                                      float* __restrict__ out)
{
    mma_gemm_tile(g_agg, Wo, out, blockIdx.x * 64);
}

// ---------------- attention over K=8 neighbors (float4, fp32 agg out) ----------
__global__ __launch_bounds__(256) void attn_kernel(const float* __restrict__ coords,
                                                   const float* __restrict__ logg)
{
    const int gq   = blockIdx.x * 8 + (threadIdx.x >> 5);
    const int b    = gq >> 13;
    const int q    = gq & (NPTS - 1);
    const int lane = threadIdx.x & 31;
    const float lg = *logg;
    const float inv_sqrt_c = 0.08838834764831845f;   // 1/sqrt(128)

    float4 qv = *(const float4*)(g_q + (size_t)gq * CH + lane * 4);

    const float* cb = coords + (size_t)b * NPTS * 3;
    const float qx = cb[q * 3 + 0], qy = cb[q * 3 + 1], qz = cb[q * 3 + 2];

    int nb[KNN];
#pragma unroll
    for (int t = 0; t < KNN; t++) nb[t] = g_idx[(size_t)gq * KNN + t];

    float sc[KNN];
#pragma unroll
    for (int t = 0; t < KNN; t++) {
        float4 kv = *(const float4*)(g_k + ((size_t)b * NPTS + nb[t]) * CH + lane * 4);
        float d = qv.x * kv.x;
        d = fmaf(qv.y, kv.y, d);
        d = fmaf(qv.z, kv.z, d);
        d = fmaf(qv.w, kv.w, d);
#pragma unroll
        for (int off = 16; off; off >>= 1) d += __shfl_xor_sync(0xffffffffu, d, off);
        float dx = qx - cb[nb[t] * 3 + 0];
        float dy = qy - cb[nb[t] * 3 + 1];
        float dz = qz - cb[nb[t] * 3 + 2];
        float d2 = fmaf(dz, dz, fmaf(dy, dy, dx * dx));
        float dist = (d2 > 0.f) ? sqrtf(d2) : 0.f;     // _safe_norm
        float gw = expf(lg * dist);
        sc[t] = d * inv_sqrt_c * gw;
    }
    float m = sc[0];
#pragma unroll
    for (int t = 1; t < KNN; t++) m = fmaxf(m, sc[t]);
    float ssum = 0.f;
#pragma unroll
    for (int t = 0; t < KNN; t++) { sc[t] = expf(sc[t] - m); ssum += sc[t]; }
    float inv = 1.f / ssum;

    float4 acc = make_float4(0.f, 0.f, 0.f, 0.f);
#pragma unroll
    for (int t = 0; t < KNN; t++) {
        float4 vv = *(const float4*)(g_v + ((size_t)b * NPTS + nb[t]) * CH + lane * 4);
        float wt = sc[t] * inv;
        acc.x = fmaf(wt, vv.x, acc.x);
        acc.y = fmaf(wt, vv.y, acc.y);
        acc.z = fmaf(wt, vv.z, acc.z);
        acc.w = fmaf(wt, vv.w, acc.w);
    }
    *(float4*)(g_agg + (size_t)gq * CH + lane * 4) = acc;
}

// ---------------- launch ----------------
extern "C" void kernel_launch(void* const* d_in, const int* in_sizes, int n_in,
                              void* d_out, int out_size)
{
    const float* feats  = (const float*)d_in[0];
    const float* coords = (const float*)d_in[1];
    const float* Wq     = (const float*)d_in[2];
    const float* Wk     = (const float*)d_in[3];
    const float* Wv     = (const float*)d_in[4];
    const float* Wo     = (const float*)d_in[5];
    const float* logg   = (const float*)d_in[6];
    float* out = (float*)d_out;

    int* idx_ptr = nullptr;
    cudaGetSymbolAddress((void**)&idx_ptr, g_idx);
    void *p_cnt = nullptr, *p_bbmin = nullptr, *p_bbmax = nullptr;
    cudaGetSymbolAddress(&p_cnt, g_cnt);
    cudaGetSymbolAddress(&p_bbmin, g_bbmin);
    cudaGetSymbolAddress(&p_bbmax, g_bbmax);

    // grid build: zero counters, bbox init (0xFF -> uint max for min; 0 for max)
    cudaMemsetAsync(p_cnt, 0, sizeof(int) * NCT, 0);
    cudaMemsetAsync(p_bbmin, 0xFF, sizeof(unsigned) * 6, 0);
    cudaMemsetAsync(p_bbmax, 0x00, sizeof(unsigned) * 6, 0);

    bbox_kernel<<<MTOT / 256, 256>>>(coords);
    grid_params_kernel<<<1, 32>>>();
    count_kernel<<<MTOT / 256, 256>>>(coords);
    scan_kernel<<<1, 1024>>>();
    scatter_kernel<<<MTOT / 256, 256>>>(coords);

    // exact grid KNN: one warp per query
    knn_grid_kernel<<<MTOT / 8, 256>>>(coords, idx_ptr);

    // q,k,v projections on tensor cores (feats + W split inline)
    qkv_mma_kernel<<<dim3(MTOT / 64, 3), 256>>>(feats, Wq, Wk, Wv);

    // neighbor attention -> g_agg (fp32)
    attn_kernel<<<MTOT / 8, 256>>>(coords, logg);

    // output projection (agg + Wo split inline)
    out_mma_kernel<<<MTOT / 64, 256>>>(Wo, out);
}

// round 12
// speedup vs baseline: 2.8041x; 2.8041x over previous
#include <cuda_runtime.h>
#include <cuda_bf16.h>
#include <math.h>

#define BATCH 2
#define NPTS  8192
#define CH    128
#define KNN   8
#define MTOT  (BATCH * NPTS)

// ---------------- scratch (no allocations allowed) ----------------
__device__ float g_q[MTOT * CH];
__device__ float g_k[MTOT * CH];
__device__ float g_v[MTOT * CH];
__device__ float g_agg[MTOT * CH];
__device__ int   g_idx[MTOT * KNN];

// ---------------- fp32 -> (hi,lo) bf16 split helpers ----------------
__device__ __forceinline__ void split_bf16(float x, unsigned short& h, unsigned short& l) {
    __nv_bfloat16 hb = __float2bfloat16(x);
    float hf = __bfloat162float(hb);
    __nv_bfloat16 lb = __float2bfloat16(x - hf);
    h = __bfloat16_as_ushort(hb);
    l = __bfloat16_as_ushort(lb);
}
__device__ __forceinline__ unsigned pack_hilo(float x) {   // X-pattern word (hi,lo)
    unsigned short h, l; split_bf16(x, h, l);
    return ((unsigned)l << 16) | (unsigned)h;
}
__device__ __forceinline__ void pack_w(float x, unsigned& p0, unsigned& p1) { // (hi,hi),(lo,lo)
    unsigned short h, l; split_bf16(x, h, l);
    p0 = ((unsigned)h << 16) | h;
    p1 = ((unsigned)l << 16) | l;
}

// ---------------- pipelined tensor-core GEMM:  Y = X @ W^T (bf16 split-K) -------
// 64x128 CTA tile, 256 threads = 8 warps (2x4), warp tile 32x32, mma.m16n8k16.
// K' = 512 bf16 in 16 chunks of 32; DOUBLE-BUFFERED smem with LDG for chunk
// kc+1 issued before MMA of chunk kc (one barrier per chunk).
// smem pitch 80B: fragment LDS banks = g*20 mod 32 + c4 -> all 32, conflict-free.
__device__ __forceinline__ void mma_gemm_tile(const float* __restrict__ X,
                                              const float* __restrict__ Wf,
                                              float* __restrict__ Y, int m0)
{
    __shared__ __align__(16) unsigned char xs[2][64 * 80];
    __shared__ __align__(16) unsigned char ws[2][128 * 80];
    const int tid  = threadIdx.x;
    const int lane = tid & 31;
    const int warp = tid >> 5;
    const int wm   = warp >> 2;       // 0..1 -> rows wm*32
    const int wn   = warp & 3;        // 0..3 -> cols wn*32
    const int g    = lane >> 2;       // 0..7
    const int c4   = lane & 3;        // 0..3

    // staging slots: X 256 slots (64 rows x 4), W 512 slots (2 per thread)
    const int xr = tid >> 2,          xf = tid & 3;
    const int wr0 = tid >> 2,         wr1 = (tid + 256) >> 2, wf = tid & 3;

    float acc[2][4][4];
#pragma unroll
    for (int i = 0; i < 2; i++)
#pragma unroll
        for (int t = 0; t < 4; t++)
#pragma unroll
            for (int r = 0; r < 4; r++) acc[i][t][r] = 0.f;

    // prologue: stage chunk 0 into buffer 0
    {
        float2 xv  = *(const float2*)(X  + (size_t)(m0 + xr) * CH + xf * 2);
        float2 wv0 = *(const float2*)(Wf + (size_t)wr0 * CH + wf * 2);
        float2 wv1 = *(const float2*)(Wf + (size_t)wr1 * CH + wf * 2);
        unsigned p0 = pack_hilo(xv.x), p1 = pack_hilo(xv.y);
        *(uint4*)(xs[0] + xr * 80 + xf * 16) = make_uint4(p0, p0, p1, p1);
        unsigned a0, a1, b0, b1;
        pack_w(wv0.x, a0, a1); pack_w(wv0.y, b0, b1);
        *(uint4*)(ws[0] + wr0 * 80 + wf * 16) = make_uint4(a0, a1, b0, b1);
        pack_w(wv1.x, a0, a1); pack_w(wv1.y, b0, b1);
        *(uint4*)(ws[0] + wr1 * 80 + wf * 16) = make_uint4(a0, a1, b0, b1);
    }
    __syncthreads();

    for (int kc = 0; kc < 16; kc++) {
        const int cur = kc & 1, nxt = cur ^ 1;
        float2 nxv, nwv0, nwv1;
        if (kc < 15) {                      // issue next chunk's loads early
            nxv  = *(const float2*)(X  + (size_t)(m0 + xr) * CH + (kc + 1) * 8 + xf * 2);
            nwv0 = *(const float2*)(Wf + (size_t)wr0 * CH + (kc + 1) * 8 + wf * 2);
            nwv1 = *(const float2*)(Wf + (size_t)wr1 * CH + (kc + 1) * 8 + wf * 2);
        }
        // compute on current buffer: 2 k16 steps
#pragma unroll
        for (int ks = 0; ks < 2; ks++) {
            unsigned a[2][4], b[4][2];
#pragma unroll
            for (int i = 0; i < 2; i++)
#pragma unroll
                for (int j = 0; j < 4; j++) {
                    int row = wm * 32 + i * 16 + g + 8 * (j & 1);
                    int off = ks * 32 + (j >> 1) * 16 + c4 * 4;
                    a[i][j] = *(const unsigned*)(xs[cur] + row * 80 + off);
                }
#pragma unroll
            for (int t = 0; t < 4; t++)
#pragma unroll
                for (int r = 0; r < 2; r++) {
                    int n   = wn * 32 + t * 8 + g;
                    int off = ks * 32 + r * 16 + c4 * 4;
                    b[t][r] = *(const unsigned*)(ws[cur] + n * 80 + off);
                }
#pragma unroll
            for (int i = 0; i < 2; i++)
#pragma unroll
                for (int t = 0; t < 4; t++)
                    asm volatile(
                        "mma.sync.aligned.m16n8k16.row.col.f32.bf16.bf16.f32 "
                        "{%0,%1,%2,%3}, {%4,%5,%6,%7}, {%8,%9}, {%0,%1,%2,%3};"
                        : "+f"(acc[i][t][0]), "+f"(acc[i][t][1]),
                          "+f"(acc[i][t][2]), "+f"(acc[i][t][3])
                        : "r"(a[i][0]), "r"(a[i][1]), "r"(a[i][2]), "r"(a[i][3]),
                          "r"(b[t][0]), "r"(b[t][1]));
        }
        if (kc < 15) {                      // stage next chunk, one barrier
            unsigned p0 = pack_hilo(nxv.x), p1 = pack_hilo(nxv.y);
            *(uint4*)(xs[nxt] + xr * 80 + xf * 16) = make_uint4(p0, p0, p1, p1);
            unsigned a0, a1, b0, b1;
            pack_w(nwv0.x, a0, a1); pack_w(nwv0.y, b0, b1);
            *(uint4*)(ws[nxt] + wr0 * 80 + wf * 16) = make_uint4(a0, a1, b0, b1);
            pack_w(nwv1.x, a0, a1); pack_w(nwv1.y, b0, b1);
            *(uint4*)(ws[nxt] + wr1 * 80 + wf * 16) = make_uint4(a0, a1, b0, b1);
            __syncthreads();
        }
    }
#pragma unroll
    for (int i = 0; i < 2; i++)
#pragma unroll
        for (int t = 0; t < 4; t++) {
            int row = m0 + wm * 32 + i * 16 + g;
            int col = wn * 32 + t * 8 + 2 * c4;
            *(float2*)(Y + (size_t)row * CH + col)       = make_float2(acc[i][t][0], acc[i][t][1]);
            *(float2*)(Y + (size_t)(row + 8) * CH + col) = make_float2(acc[i][t][2], acc[i][t][3]);
        }
}

__global__ __launch_bounds__(256) void qkv_mma_kernel(const float* __restrict__ feats,
                                                      const float* __restrict__ Wq,
                                                      const float* __restrict__ Wk,
                                                      const float* __restrict__ Wv)
{
    int w = blockIdx.y;
    const float* W = (w == 0) ? Wq : (w == 1) ? Wk : Wv;
    float* Y = (w == 0) ? g_q : (w == 1) ? g_k : g_v;
    mma_gemm_tile(feats, W, Y, blockIdx.x * 64);
}

__global__ __launch_bounds__(256) void out_mma_kernel(const float* __restrict__ Wo,
                                                      float* __restrict__ out)
{
    mma_gemm_tile(g_agg, Wo, out, blockIdx.x * 64);
}

// ---------------- KNN (R9 proven): scalar fast path + ballot-walk insert --------
// e-space ordering: e = csq - 2*dot (query-constant shift of d2; same top-k set).
#define QW  4
#define CCH 2048

__device__ __forceinline__ void try_insert4(float d2, int base,
                                            float& val, int& idx, float& thr)
{
    const unsigned full = 0xffffffffu;
    unsigned m = __ballot_sync(full, d2 < thr);
    const int lane = threadIdx.x & 31;
    while (m) {
        int src = __ffs(m) - 1;
        m &= m - 1;
        float dn = __shfl_sync(full, d2, src);
        if (dn < thr) {                         // warp-uniform
            int   in = base + (src << 2);
            float pv = __shfl_up_sync(full, val, 1);
            int   pi = __shfl_up_sync(full, idx, 1);
            unsigned le = __ballot_sync(full, val <= dn);
            int pos = __popc(le & 0xff);
            if (lane == pos)                  { val = dn; idx = in; }
            else if (lane > pos && lane < 8)  { val = pv; idx = pi; }
            thr = __shfl_sync(full, val, 7);
        }
    }
}

__global__ __launch_bounds__(256, 3) void knn_kernel(const float* __restrict__ coords,
                                                     int* __restrict__ out_idx)
{
    __shared__ float sx[CCH], sy[CCH], sz[CCH], ss[CCH];
    const unsigned full = 0xffffffffu;
    const int b     = blockIdx.y;
    const int warp  = threadIdx.x >> 5;
    const int lane  = threadIdx.x & 31;
    const int qbase = blockIdx.x * (8 * QW) + warp * QW;
    const float* cb = coords + (size_t)b * NPTS * 3;

    float m2x[QW], m2y[QW], m2z[QW];
#pragma unroll
    for (int u = 0; u < QW; u++) {
        m2x[u] = -2.f * cb[(qbase + u) * 3 + 0];
        m2y[u] = -2.f * cb[(qbase + u) * 3 + 1];
        m2z[u] = -2.f * cb[(qbase + u) * 3 + 2];
    }

    float val[QW], thr[QW];
    int idx[QW];
#pragma unroll
    for (int u = 0; u < QW; u++) { val[u] = 3.0e38f; thr[u] = 3.0e38f; idx[u] = -1; }

    for (int c0 = 0; c0 < NPTS; c0 += CCH) {
        __syncthreads();
        for (int t = threadIdx.x; t < CCH; t += 256) {
            float x = cb[(c0 + t) * 3 + 0];
            float y = cb[(c0 + t) * 3 + 1];
            float z = cb[(c0 + t) * 3 + 2];
            sx[t] = x; sy[t] = y; sz[t] = z;
            ss[t] = fmaf(z, z, fmaf(y, y, x * x));
        }
        __syncthreads();

        for (int j0 = 0; j0 < CCH; j0 += 128) {
            int base = j0 + lane * 4;
            float4 cx = *(const float4*)&sx[base];
            float4 cy = *(const float4*)&sy[base];
            float4 cz = *(const float4*)&sz[base];
            float4 cs = *(const float4*)&ss[base];
            int jb = c0 + j0;                        // warp-uniform
#pragma unroll
            for (int u = 0; u < QW; u++) {
                float e0 = fmaf(m2z[u], cz.x, fmaf(m2y[u], cy.x, fmaf(m2x[u], cx.x, cs.x)));
                float e1 = fmaf(m2z[u], cz.y, fmaf(m2y[u], cy.y, fmaf(m2x[u], cx.y, cs.y)));
                float e2 = fmaf(m2z[u], cz.z, fmaf(m2y[u], cy.z, fmaf(m2x[u], cx.z, cs.z)));
                float e3 = fmaf(m2z[u], cz.w, fmaf(m2y[u], cy.w, fmaf(m2x[u], cx.w, cs.w)));
                float lm = fminf(fminf(e0, e1), fminf(e2, e3));
                if (__any_sync(full, lm < thr[u])) {
                    try_insert4(e0, jb + 0, val[u], idx[u], thr[u]);
                    try_insert4(e1, jb + 1, val[u], idx[u], thr[u]);
                    try_insert4(e2, jb + 2, val[u], idx[u], thr[u]);
                    try_insert4(e3, jb + 3, val[u], idx[u], thr[u]);
                }
            }
        }
    }

    if (lane < KNN) {
#pragma unroll
        for (int u = 0; u < QW; u++)
            out_idx[((size_t)b * NPTS + qbase + u) * KNN + lane] = idx[u];
    }
}

// ---------------- attention over K=8 neighbors (float4, fp32 agg out) ----------
__global__ __launch_bounds__(256) void attn_kernel(const float* __restrict__ coords,
                                                   const float* __restrict__ logg)
{
    const int gq   = blockIdx.x * 8 + (threadIdx.x >> 5);
    const int b    = gq >> 13;
    const int q    = gq & (NPTS - 1);
    const int lane = threadIdx.x & 31;
    const float lg = *logg;
    const float inv_sqrt_c = 0.08838834764831845f;   // 1/sqrt(128)

    float4 qv = *(const float4*)(g_q + (size_t)gq * CH + lane * 4);

    const float* cb = coords + (size_t)b * NPTS * 3;
    const float qx = cb[q * 3 + 0], qy = cb[q * 3 + 1], qz = cb[q * 3 + 2];

    int nb[KNN];
#pragma unroll
    for (int t = 0; t < KNN; t++) nb[t] = g_idx[(size_t)gq * KNN + t];

    float sc[KNN];
#pragma unroll
    for (int t = 0; t < KNN; t++) {
        float4 kv = *(const float4*)(g_k + ((size_t)b * NPTS + nb[t]) * CH + lane * 4);
        float d = qv.x * kv.x;
        d = fmaf(qv.y, kv.y, d);
        d = fmaf(qv.z, kv.z, d);
        d = fmaf(qv.w, kv.w, d);
#pragma unroll
        for (int off = 16; off; off >>= 1) d += __shfl_xor_sync(0xffffffffu, d, off);
        float dx = qx - cb[nb[t] * 3 + 0];
        float dy = qy - cb[nb[t] * 3 + 1];
        float dz = qz - cb[nb[t] * 3 + 2];
        float d2 = fmaf(dz, dz, fmaf(dy, dy, dx * dx));
        float dist = (d2 > 0.f) ? sqrtf(d2) : 0.f;     // _safe_norm
        float gw = expf(lg * dist);
        sc[t] = d * inv_sqrt_c * gw;
    }
    float m = sc[0];
#pragma unroll
    for (int t = 1; t < KNN; t++) m = fmaxf(m, sc[t]);
    float ssum = 0.f;
#pragma unroll
    for (int t = 0; t < KNN; t++) { sc[t] = expf(sc[t] - m); ssum += sc[t]; }
    float inv = 1.f / ssum;

    float4 acc = make_float4(0.f, 0.f, 0.f, 0.f);
#pragma unroll
    for (int t = 0; t < KNN; t++) {
        float4 vv = *(const float4*)(g_v + ((size_t)b * NPTS + nb[t]) * CH + lane * 4);
        float wt = sc[t] * inv;
        acc.x = fmaf(wt, vv.x, acc.x);
        acc.y = fmaf(wt, vv.y, acc.y);
        acc.z = fmaf(wt, vv.z, acc.z);
        acc.w = fmaf(wt, vv.w, acc.w);
    }
    *(float4*)(g_agg + (size_t)gq * CH + lane * 4) = acc;
}

// ---------------- launch ----------------
extern "C" void kernel_launch(void* const* d_in, const int* in_sizes, int n_in,
                              void* d_out, int out_size)
{
    const float* feats  = (const float*)d_in[0];
    const float* coords = (const float*)d_in[1];
    const float* Wq     = (const float*)d_in[2];
    const float* Wk     = (const float*)d_in[3];
    const float* Wv     = (const float*)d_in[4];
    const float* Wo     = (const float*)d_in[5];
    const float* logg   = (const float*)d_in[6];
    float* out = (float*)d_out;

    int* idx_ptr = nullptr;
    cudaGetSymbolAddress((void**)&idx_ptr, g_idx);

    // KNN top-8 per query (32 queries/CTA)
    knn_kernel<<<dim3(NPTS / 32, BATCH), 256>>>(coords, idx_ptr);

    // q,k,v projections on tensor cores (pipelined, feats + W split inline)
    qkv_mma_kernel<<<dim3(MTOT / 64, 3), 256>>>(feats, Wq, Wk, Wv);

    // neighbor attention -> g_agg (fp32)
    attn_kernel<<<MTOT / 8, 256>>>(coords, logg);

    // output projection (pipelined, agg + Wo split inline)
    out_mma_kernel<<<MTOT / 64, 256>>>(Wo, out);
}